// round 1
// baseline (speedup 1.0000x reference)
#include <cuda_runtime.h>
#include <math.h>

#define N_PTS 8192
#define TILE  1024
#define WARPS_PER_BLOCK 16
#define THREADS_PER_BLOCK (WARPS_PER_BLOCK * 32)
#define ROWS_PER_WARP 2
#define ROWS_PER_BLOCK (WARPS_PER_BLOCK * ROWS_PER_WARP)   // 32
#define NBLOCKS (N_PTS / ROWS_PER_BLOCK)                    // 256

#define THR2 4.0e-4f        // MAX_ALIGN_DIST^2
#define BIGF 1.0e30f

// Per-row intermediates (device globals: no allocation allowed)
__device__ float g_density[N_PTS];
__device__ float g_align_sum[N_PTS];
__device__ int   g_align_cnt[N_PTS];

__device__ __forceinline__ void insert9(float (&t)[9], float d) {
    if (d < t[8]) {
        t[8] = d;
        #pragma unroll
        for (int k = 8; k > 0; --k) {
            float lo = fminf(t[k - 1], t[k]);
            float hi = fmaxf(t[k - 1], t[k]);
            t[k - 1] = lo;
            t[k]     = hi;
        }
    }
}

// Extract the 9 smallest d2 across the warp's 32 sorted per-lane lists,
// convert each to a distance, return mean of the 8 largest of those 9
// (i.e., drop the global min = the self-distance).
__device__ __forceinline__ float knn_mean(float (&t)[9], int lane) {
    float sum = 0.0f;
    float mn  = 0.0f;
    #pragma unroll
    for (int r = 0; r < 9; ++r) {
        float cand = t[0];
        float v = cand;
        #pragma unroll
        for (int off = 16; off > 0; off >>= 1)
            v = fminf(v, __shfl_xor_sync(0xffffffffu, v, off));
        unsigned m = __ballot_sync(0xffffffffu, cand == v);
        if (lane == (__ffs(m) - 1)) {
            // pop front of this lane's sorted list
            #pragma unroll
            for (int k = 0; k < 8; ++k) t[k] = t[k + 1];
            t[8] = BIGF;
        }
        float d = sqrtf(fmaxf(v, 0.0f) + 1e-12f);
        if (r == 0) mn = d;   // extraction is ascending -> first is global min
        sum += d;
    }
    return (sum - mn) * 0.125f;
}

__global__ __launch_bounds__(THREADS_PER_BLOCK)
void pair_kernel(const float*  __restrict__ pos,
                 const float4* __restrict__ rot,
                 const float*  __restrict__ opacity) {
    __shared__ float4 s_p[TILE];   // x, y, z, |p|^2
    __shared__ float4 s_q[TILE];   // quaternion

    const int lane = threadIdx.x & 31;
    const int warp = threadIdx.x >> 5;
    const int i0 = blockIdx.x * ROWS_PER_BLOCK + warp * ROWS_PER_WARP;
    const int i1 = i0 + 1;

    const float x0 = pos[3 * i0 + 0], y0 = pos[3 * i0 + 1], z0 = pos[3 * i0 + 2];
    const float x1 = pos[3 * i1 + 0], y1 = pos[3 * i1 + 1], z1 = pos[3 * i1 + 2];
    const float sq0 = fmaf(x0, x0, fmaf(y0, y0, z0 * z0));
    const float sq1 = fmaf(x1, x1, fmaf(y1, y1, z1 * z1));
    const float4 q0 = rot[i0];
    const float4 q1 = rot[i1];

    float t0[9], t1[9];
    #pragma unroll
    for (int k = 0; k < 9; ++k) { t0[k] = BIGF; t1[k] = BIGF; }
    float as0 = 0.0f, as1 = 0.0f;
    int   ac0 = 0,    ac1 = 0;

    for (int base = 0; base < N_PTS; base += TILE) {
        // cooperative tile load
        for (int t = threadIdx.x; t < TILE; t += THREADS_PER_BLOCK) {
            int j = base + t;
            float px = pos[3 * j + 0], py = pos[3 * j + 1], pz = pos[3 * j + 2];
            s_p[t] = make_float4(px, py, pz, fmaf(px, px, fmaf(py, py, pz * pz)));
            s_q[t] = rot[j];
        }
        __syncthreads();

        #pragma unroll 4
        for (int t = lane; t < TILE; t += 32) {
            float4 p = s_p[t];
            int j = base + t;
            float dot0 = fmaf(x0, p.x, fmaf(y0, p.y, z0 * p.z));
            float dot1 = fmaf(x1, p.x, fmaf(y1, p.y, z1 * p.z));
            float d20 = fmaf(-2.0f, dot0, sq0 + p.w);
            float d21 = fmaf(-2.0f, dot1, sq1 + p.w);
            insert9(t0, d20);
            insert9(t1, d21);
            bool nb0 = (d20 < THR2) && (j != i0);
            bool nb1 = (d21 < THR2) && (j != i1);
            if (nb0 | nb1) {                       // rare (~10/8192)
                float4 q = s_q[t];
                if (nb0) {
                    float qd = fmaf(q0.x, q.x, fmaf(q0.y, q.y, fmaf(q0.z, q.z, q0.w * q.w)));
                    as0 += 1.0f - fabsf(qd);
                    ac0++;
                }
                if (nb1) {
                    float qd = fmaf(q1.x, q.x, fmaf(q1.y, q.y, fmaf(q1.z, q.z, q1.w * q.w)));
                    as1 += 1.0f - fabsf(qd);
                    ac1++;
                }
            }
        }
        __syncthreads();
    }

    // per-row kNN mean (warp-collective)
    float knn0 = knn_mean(t0, lane);
    float knn1 = knn_mean(t1, lane);

    // warp-reduce alignment partials
    #pragma unroll
    for (int off = 16; off > 0; off >>= 1) {
        as0 += __shfl_xor_sync(0xffffffffu, as0, off);
        as1 += __shfl_xor_sync(0xffffffffu, as1, off);
        ac0 += __shfl_xor_sync(0xffffffffu, ac0, off);
        ac1 += __shfl_xor_sync(0xffffffffu, ac1, off);
    }

    if (lane == 0) {
        g_align_sum[i0] = as0;
        g_align_sum[i1] = as1;
        g_align_cnt[i0] = ac0;
        g_align_cnt[i1] = ac1;
        g_density[i0] = fabsf(knn0 - 0.01f) * opacity[i0];
        g_density[i1] = fabsf(knn1 - 0.01f) * opacity[i1];
    }
}

__global__ __launch_bounds__(1024)
void final_kernel(const float* __restrict__ scales, float* __restrict__ out) {
    __shared__ double s_f[32], s_d[32], s_a[32], s_c[32];
    const int tid  = threadIdx.x;
    const int lane = tid & 31;
    const int wid  = tid >> 5;

    double fs = 0.0, ds = 0.0, as = 0.0, cs = 0.0;
    for (int i = tid; i < N_PTS; i += 1024) {
        float a = expf(scales[3 * i + 0]);
        float b = expf(scales[3 * i + 1]);
        float c = expf(scales[3 * i + 2]);
        float t;
        if (a > b) { t = a; a = b; b = t; }
        if (b > c) { t = b; b = c; c = t; }
        if (a > b) { t = a; a = b; b = t; }
        // a <= b <= c : smallest, middle, largest
        float aspect = c / (a + 1e-8f);
        float fr = logf(aspect + 1e-8f);
        float disc = 1.0f / (fabsf(c - b) + 0.001f);
        fs += (double)(fr + 0.1f * disc);
        ds += (double)g_density[i];
        as += (double)g_align_sum[i];
        cs += (double)g_align_cnt[i];
    }
    #pragma unroll
    for (int off = 16; off > 0; off >>= 1) {
        fs += __shfl_down_sync(0xffffffffu, fs, off);
        ds += __shfl_down_sync(0xffffffffu, ds, off);
        as += __shfl_down_sync(0xffffffffu, as, off);
        cs += __shfl_down_sync(0xffffffffu, cs, off);
    }
    if (lane == 0) { s_f[wid] = fs; s_d[wid] = ds; s_a[wid] = as; s_c[wid] = cs; }
    __syncthreads();
    if (wid == 0) {
        fs = s_f[lane]; ds = s_d[lane]; as = s_a[lane]; cs = s_c[lane];
        #pragma unroll
        for (int off = 16; off > 0; off >>= 1) {
            fs += __shfl_down_sync(0xffffffffu, fs, off);
            ds += __shfl_down_sync(0xffffffffu, ds, off);
            as += __shfl_down_sync(0xffffffffu, as, off);
            cs += __shfl_down_sync(0xffffffffu, cs, off);
        }
        if (lane == 0) {
            double flatness_loss = -(fs / (double)N_PTS);
            double alignment_loss = (cs > 0.0) ? (as / cs) : 0.0;
            double density_loss = ds / (double)N_PTS;
            out[0] = (float)(1.0 * flatness_loss + 0.5 * alignment_loss + 0.2 * density_loss);
        }
    }
}

extern "C" void kernel_launch(void* const* d_in, const int* in_sizes, int n_in,
                              void* d_out, int out_size) {
    const float*  positions = (const float*)d_in[0];
    const float4* rotations = (const float4*)d_in[1];
    const float*  scales    = (const float*)d_in[2];
    const float*  opacity   = (const float*)d_in[3];
    float* out = (float*)d_out;

    pair_kernel<<<NBLOCKS, THREADS_PER_BLOCK>>>(positions, rotations, opacity);
    final_kernel<<<1, 1024>>>(scales, out);
}

// round 2
// speedup vs baseline: 2.9651x; 2.9651x over previous
#include <cuda_runtime.h>
#include <math.h>

#define N_PTS   8192
#define GDIM    8
#define NCELLS  (GDIM * GDIM * GDIM)          // 512
#define CELL_H  0.0375f
#define INV_H   26.666666666666668f
#define H2      0.00140625f                    // CELL_H^2
#define THR2    4.0e-4f                        // MAX_ALIGN_DIST^2
#define BIGF    1.0e30f

// ---------------- device scratch (no allocations allowed) ----------------
__device__ int    g_cnt[NCELLS];
__device__ int    g_startc[NCELLS + 1];
__device__ int    g_cid[N_PTS];
__device__ int    g_rank[N_PTS];
__device__ int    g_orig[N_PTS];      // sorted slot -> original index
__device__ int    g_cid_s[N_PTS];     // sorted slot -> cell id
__device__ float4 g_sp[N_PTS];        // sorted positions (x,y,z,|p|^2)
__device__ float4 g_sq[N_PTS];        // sorted quaternions
__device__ float  g_density[N_PTS];
__device__ float  g_align_sum[N_PTS];
__device__ float  g_align_cnt[N_PTS];
__device__ int    g_flag[N_PTS];
__device__ float  g_part[32][4];

// ---------------- helpers ----------------
__device__ __forceinline__ void insert9(float (&t)[9], float d) {
    if (d < t[8]) {
        t[8] = d;
        #pragma unroll
        for (int k = 8; k > 0; --k) {
            float lo = fminf(t[k - 1], t[k]);
            float hi = fmaxf(t[k - 1], t[k]);
            t[k - 1] = lo;
            t[k]     = hi;
        }
    }
}

// Warp-collective: extract the 9 smallest d2 across the warp's per-lane sorted
// lists; return mean of distances excluding the global min (the self-distance).
// Also reports the 9th-smallest d2 for validity checking.
__device__ __forceinline__ float knn_mean(float (&t)[9], int lane, float* ninth_d2) {
    float sum = 0.0f, mn = 0.0f, last = 0.0f;
    #pragma unroll
    for (int r = 0; r < 9; ++r) {
        float cand = t[0];
        float v = cand;
        #pragma unroll
        for (int off = 16; off > 0; off >>= 1)
            v = fminf(v, __shfl_xor_sync(0xffffffffu, v, off));
        unsigned m = __ballot_sync(0xffffffffu, cand == v);
        if (lane == (__ffs(m) - 1)) {
            #pragma unroll
            for (int k = 0; k < 8; ++k) t[k] = t[k + 1];
            t[8] = BIGF;
        }
        float d = sqrtf(fmaxf(v, 0.0f) + 1e-12f);
        if (r == 0) mn = d;
        if (r == 8) last = v;
        sum += d;
    }
    *ninth_d2 = last;
    return (sum - mn) * 0.125f;
}

// ---------------- binning ----------------
__global__ void zero_k() {
    g_cnt[threadIdx.x] = 0;
}

__global__ void count_k(const float* __restrict__ pos) {
    int i = blockIdx.x * blockDim.x + threadIdx.x;
    float x = pos[3 * i + 0], y = pos[3 * i + 1], z = pos[3 * i + 2];
    int cx = min(GDIM - 1, max(0, (int)(x * INV_H)));
    int cy = min(GDIM - 1, max(0, (int)(y * INV_H)));
    int cz = min(GDIM - 1, max(0, (int)(z * INV_H)));
    int cid = (cz * GDIM + cy) * GDIM + cx;
    g_cid[i]  = cid;
    g_rank[i] = atomicAdd(&g_cnt[cid], 1);
}

__global__ void scan_k() {
    __shared__ int sh[NCELLS];
    int t = threadIdx.x;
    sh[t] = g_cnt[t];
    __syncthreads();
    #pragma unroll
    for (int off = 1; off < NCELLS; off <<= 1) {
        int add = (t >= off) ? sh[t - off] : 0;
        __syncthreads();
        sh[t] += add;
        __syncthreads();
    }
    g_startc[t + 1] = sh[t];
    if (t == 0) g_startc[0] = 0;
}

__global__ void scatter_k(const float* __restrict__ pos,
                          const float4* __restrict__ rot) {
    int i = blockIdx.x * blockDim.x + threadIdx.x;
    int cid = g_cid[i];
    int dst = g_startc[cid] + g_rank[i];
    float x = pos[3 * i + 0], y = pos[3 * i + 1], z = pos[3 * i + 2];
    g_sp[dst]    = make_float4(x, y, z, fmaf(x, x, fmaf(y, y, z * z)));
    g_sq[dst]    = rot[i];
    g_orig[dst]  = i;
    g_cid_s[dst] = cid;
}

// ---------------- main: one warp per (sorted) row ----------------
__global__ __launch_bounds__(256)
void main_k(const float* __restrict__ opacity) {
    int gw   = (blockIdx.x * blockDim.x + threadIdx.x) >> 5;  // sorted row s
    int lane = threadIdx.x & 31;
    int s = gw;

    float4 P = g_sp[s];
    float4 Q = g_sq[s];
    int cid = g_cid_s[s];
    int cx = cid & (GDIM - 1);
    int cy = (cid >> 3) & (GDIM - 1);
    int cz = cid >> 6;

    float t[9];
    #pragma unroll
    for (int k = 0; k < 9; ++k) t[k] = H2;   // sentinel = h^2 (validity gate)
    float asum = 0.0f, acnt = 0.0f;

    int x0 = max(cx - 1, 0), x1 = min(cx + 1, GDIM - 1);
    int y0 = max(cy - 1, 0), y1 = min(cy + 1, GDIM - 1);
    int z0 = max(cz - 1, 0), z1 = min(cz + 1, GDIM - 1);

    for (int z = z0; z <= z1; ++z) {
        for (int y = y0; y <= y1; ++y) {
            int rowb = (z * GDIM + y) * GDIM;
            int jb = g_startc[rowb + x0];
            int je = g_startc[rowb + x1 + 1];
            for (int j = jb + lane; j < je; j += 32) {
                float4 p = g_sp[j];
                float dot = fmaf(P.x, p.x, fmaf(P.y, p.y, P.z * p.z));
                float d2  = fmaf(-2.0f, dot, P.w + p.w);
                insert9(t, d2);
                if (d2 < THR2 && j != s) {        // alignment: exact (0.02 < h)
                    float4 q = g_sq[j];
                    float qd = fmaf(Q.x, q.x, fmaf(Q.y, q.y, fmaf(Q.z, q.z, Q.w * q.w)));
                    asum += 1.0f - fabsf(qd);
                    acnt += 1.0f;
                }
            }
        }
    }

    #pragma unroll
    for (int off = 16; off > 0; off >>= 1) {
        asum += __shfl_xor_sync(0xffffffffu, asum, off);
        acnt += __shfl_xor_sync(0xffffffffu, acnt, off);
    }

    float ninth;
    float knn = knn_mean(t, lane, &ninth);

    if (lane == 0) {
        int orig = g_orig[s];
        g_align_sum[orig] = asum;
        g_align_cnt[orig] = acnt;
        int bad = (ninth >= H2);                   // sentinel survived -> <9 within h
        g_flag[orig] = bad;
        g_density[orig] = bad ? 0.0f : fabsf(knn - 0.01f) * opacity[orig];
    }
}

// ---------------- fallback: brute force for flagged rows ----------------
__global__ __launch_bounds__(256)
void fallback_k(const float* __restrict__ pos,
                const float* __restrict__ opacity) {
    int gw   = (blockIdx.x * blockDim.x + threadIdx.x) >> 5;  // 0..2047
    int lane = threadIdx.x & 31;
    for (int r = gw; r < N_PTS; r += 2048) {
        if (!g_flag[r]) continue;
        float x = pos[3 * r + 0], y = pos[3 * r + 1], z = pos[3 * r + 2];
        float sq = fmaf(x, x, fmaf(y, y, z * z));
        float t[9];
        #pragma unroll
        for (int k = 0; k < 9; ++k) t[k] = BIGF;
        for (int j = lane; j < N_PTS; j += 32) {
            float4 p = g_sp[j];                    // sorted copy: coalesced f4
            float dot = fmaf(x, p.x, fmaf(y, p.y, z * p.z));
            float d2  = fmaf(-2.0f, dot, sq + p.w);
            insert9(t, d2);
        }
        float ninth;
        float knn = knn_mean(t, lane, &ninth);
        if (lane == 0)
            g_density[r] = fabsf(knn - 0.01f) * opacity[r];
    }
}

// ---------------- reductions (fp32 tree) ----------------
__global__ __launch_bounds__(256)
void red1_k(const float* __restrict__ scales) {
    __shared__ float sf[8][4];
    int tid = threadIdx.x, lane = tid & 31, wid = tid >> 5;
    int i = blockIdx.x * 256 + tid;

    float a = expf(scales[3 * i + 0]);
    float b = expf(scales[3 * i + 1]);
    float c = expf(scales[3 * i + 2]);
    float t;
    if (a > b) { t = a; a = b; b = t; }
    if (b > c) { t = b; b = c; c = t; }
    if (a > b) { t = a; a = b; b = t; }
    float aspect = c / (a + 1e-8f);
    float fr = logf(aspect + 1e-8f) + 0.1f / (fabsf(c - b) + 0.001f);
    float ds = g_density[i];
    float as = g_align_sum[i];
    float cs = g_align_cnt[i];

    #pragma unroll
    for (int off = 16; off > 0; off >>= 1) {
        fr += __shfl_down_sync(0xffffffffu, fr, off);
        ds += __shfl_down_sync(0xffffffffu, ds, off);
        as += __shfl_down_sync(0xffffffffu, as, off);
        cs += __shfl_down_sync(0xffffffffu, cs, off);
    }
    if (lane == 0) { sf[wid][0] = fr; sf[wid][1] = ds; sf[wid][2] = as; sf[wid][3] = cs; }
    __syncthreads();
    if (tid == 0) {
        float F = 0, D = 0, A = 0, C = 0;
        #pragma unroll
        for (int w = 0; w < 8; ++w) { F += sf[w][0]; D += sf[w][1]; A += sf[w][2]; C += sf[w][3]; }
        g_part[blockIdx.x][0] = F;
        g_part[blockIdx.x][1] = D;
        g_part[blockIdx.x][2] = A;
        g_part[blockIdx.x][3] = C;
    }
}

__global__ void red2_k(float* __restrict__ out) {
    int lane = threadIdx.x;
    float F = g_part[lane][0], D = g_part[lane][1];
    float A = g_part[lane][2], C = g_part[lane][3];
    #pragma unroll
    for (int off = 16; off > 0; off >>= 1) {
        F += __shfl_down_sync(0xffffffffu, F, off);
        D += __shfl_down_sync(0xffffffffu, D, off);
        A += __shfl_down_sync(0xffffffffu, A, off);
        C += __shfl_down_sync(0xffffffffu, C, off);
    }
    if (lane == 0) {
        float flatness_loss  = -(F / (float)N_PTS);
        float alignment_loss = (C > 0.0f) ? (A / C) : 0.0f;
        float density_loss   = D / (float)N_PTS;
        out[0] = 1.0f * flatness_loss + 0.5f * alignment_loss + 0.2f * density_loss;
    }
}

// ---------------- launch ----------------
extern "C" void kernel_launch(void* const* d_in, const int* in_sizes, int n_in,
                              void* d_out, int out_size) {
    const float*  positions = (const float*)d_in[0];
    const float4* rotations = (const float4*)d_in[1];
    const float*  scales    = (const float*)d_in[2];
    const float*  opacity   = (const float*)d_in[3];
    float* out = (float*)d_out;

    zero_k<<<1, NCELLS>>>();
    count_k<<<N_PTS / 256, 256>>>(positions);
    scan_k<<<1, NCELLS>>>();
    scatter_k<<<N_PTS / 256, 256>>>(positions, rotations);
    main_k<<<N_PTS / 8, 256>>>(opacity);          // 1 warp per row
    fallback_k<<<64, 256>>>(positions, opacity);  // 2048 warps, strided rows
    red1_k<<<32, 256>>>(scales);
    red2_k<<<1, 32>>>(out);
}